// round 16
// baseline (speedup 1.0000x reference)
#include <cuda_runtime.h>
#include <cuda_fp16.h>
#include <cstdint>

// ============================================================================
// C[8192,4096] = X[8192,4096] @ W[4096,4096], fp32 in/out.
// R13 (3rd submit; two prior container-level infra failures, never compiled):
//      R12 fp16 kernel + iteration reorder: after the barrier, load the ks0
//      ldmatrix fragments BEFORE issuing the 16 cp.asyncs for the next stage.
//      The cp.async issue burst (~8 cyc/op structural on the LSU) was sitting
//      between the barrier and the first MMA; now it hides under the MMA
//      burst and the tensor pipe restarts ~100+ cyc earlier per iteration.
//      Sync skeleton unchanged (wait -> sync -> ... -> compute, proven).
// ============================================================================
#define M_DIM 8192
#define K_DIM 4096
#define N_DIM 4096

#define BM 128
#define BN 128
#define BK 64                         // 64 halves = 128 B rows
#define STAGES 3
#define ITERS (K_DIM / BK)            // 64
#define NT (N_DIM / BN)               // 32
#define MT (M_DIM / BM)               // 64
#define THREADS 256

#define A_BYTES (BM * BK * 2)         // 16384
#define B_BYTES (BN * BK * 2)         // 16384
#define STAGE_BYTES (A_BYTES + B_BYTES)   // 32768
#define SMEM_TOTAL (STAGES * STAGE_BYTES) // 98304

__device__ __half g_Bth[(size_t)N_DIM * K_DIM];  // 32 MB (fp16 W^T, [N,K])
__device__ __half g_Xh [(size_t)M_DIM * K_DIM];  // 64 MB (fp16 X)

// ============================================================================
// PTX helpers
// ============================================================================
__device__ __forceinline__ uint32_t smem_to_u32(const void* p) {
    uint32_t a;
    asm("{ .reg .u64 t; cvta.to.shared.u64 t, %1; cvt.u32.u64 %0, t; }"
        : "=r"(a) : "l"(p));
    return a;
}

#define CP_ASYNC16(smem_addr, gptr) \
    asm volatile("cp.async.cg.shared.global [%0], [%1], 16;" \
                 :: "r"(smem_addr), "l"(gptr) : "memory")
#define CP_COMMIT() asm volatile("cp.async.commit_group;" ::: "memory")
#define CP_WAIT(n)  asm volatile("cp.async.wait_group %0;" :: "n"(n) : "memory")

#define LDSM_X4(r0, r1, r2, r3, addr) \
    asm volatile("ldmatrix.sync.aligned.m8n8.x4.shared.b16 {%0,%1,%2,%3}, [%4];" \
                 : "=r"(r0), "=r"(r1), "=r"(r2), "=r"(r3) : "r"(addr))

#define MMA_F16(c, a, b) \
    asm volatile( \
        "mma.sync.aligned.m16n8k16.row.col.f32.f16.f16.f32 " \
        "{%0,%1,%2,%3}, {%4,%5,%6,%7}, {%8,%9}, {%0,%1,%2,%3};" \
        : "+f"((c)[0]), "+f"((c)[1]), "+f"((c)[2]), "+f"((c)[3]) \
        : "r"((a)[0]), "r"((a)[1]), "r"((a)[2]), "r"((a)[3]), \
          "r"((b)[0]), "r"((b)[1]))

// ============================================================================
// Kernel 0 (fused preprocessing):
//   blocks [0, NXB): convert X -> fp16 (8 floats -> 8 halves per thread)
//   blocks [NXB, NXB+NTB): transpose W[k][n] -> fp16 Bt[n][k] (32x32 tiles)
// ============================================================================
#define NXB ((M_DIM * (size_t)K_DIM / 8) / 256)      // 16384
#define NTB ((K_DIM / 32) * (N_DIM / 32))            // 16384

__global__ void __launch_bounds__(256) preprocess_kernel(
    const float4* __restrict__ X, uint4* __restrict__ Xh,
    const float* __restrict__ W, __half* __restrict__ Bt)
{
    __shared__ float t[32][33];
    unsigned bid = blockIdx.x;
    int tid = threadIdx.x;

    if (bid < NXB) {
        size_t i = (size_t)bid * 256 + tid;
        float4 v0 = X[2 * i];
        float4 v1 = X[2 * i + 1];
        __half2 h0 = __floats2half2_rn(v0.x, v0.y);
        __half2 h1 = __floats2half2_rn(v0.z, v0.w);
        __half2 h2 = __floats2half2_rn(v1.x, v1.y);
        __half2 h3 = __floats2half2_rn(v1.z, v1.w);
        uint4 out;
        out.x = *(uint32_t*)&h0;  out.y = *(uint32_t*)&h1;
        out.z = *(uint32_t*)&h2;  out.w = *(uint32_t*)&h3;
        Xh[i] = out;
    } else {
        unsigned b2 = bid - NXB;
        int bx = (b2 % (N_DIM / 32)) * 32;   // n block
        int by = (b2 / (N_DIM / 32)) * 32;   // k block
        int tx = tid & 31, ty = tid >> 5;    // 32 x 8
        #pragma unroll
        for (int j = 0; j < 32; j += 8)
            t[ty + j][tx] = W[(size_t)(by + ty + j) * N_DIM + (bx + tx)];
        __syncthreads();
        #pragma unroll
        for (int j = 0; j < 32; j += 8)
            Bt[(size_t)(bx + ty + j) * K_DIM + (by + tx)] =
                __float2half_rn(t[tx][ty + j]);
    }
}

// ============================================================================
// Kernel 1: fp16 mma.sync GEMM, 3-stage cp.async pipeline, 2 CTAs/SM
//   256 threads = 8 warps in 4(m) x 2(n); warp tile 32x64
//   Per-iter order: wait -> sync -> LDSM ks0 -> issue cp.async -> MMAs
// ============================================================================
__global__ void __launch_bounds__(THREADS, 2) gemm_f16_kernel(
    const __half* __restrict__ X,
    const __half* __restrict__ Bt,
    float* __restrict__ C)
{
    extern __shared__ __align__(1024) char smem[];
    uint32_t sb = smem_to_u32(smem);

    int tid  = threadIdx.x;
    int wid  = tid >> 5;
    int lane = tid & 31;
    int bid  = blockIdx.x;
    int tn   = bid % NT;
    int tm   = bid / NT;

    int wm = wid & 3;              // m group 0..3
    int wn = wid >> 2;             // n group 0..1
    int warp_m0 = wm * 32;
    int warp_n0 = wn * 64;

    // ---- cp.async precompute (4 chunks of 16B per operand per thread) ----
    uint32_t offA[4]; const __half* pA[4];
    uint32_t offB[4]; const __half* pB[4];
    #pragma unroll
    for (int p = 0; p < 4; p++) {
        int ca = tid + p * THREADS;
        int row = ca >> 3, c = ca & 7;
        uint32_t off = row * 128 + ((c ^ (row & 7)) << 4);
        offA[p] = off;
        offB[p] = off;
        pA[p] = X  + (size_t)(tm * BM + row) * K_DIM + c * 8;
        pB[p] = Bt + (size_t)(tn * BN + row) * K_DIM + c * 8;
    }

    // ---- ldmatrix per-lane address components ----
    uint32_t a_rel = (uint32_t)(warp_m0 + (lane & 15)) * 128;
    uint32_t a_sw  = lane & 7;
    uint32_t a_co  = lane >> 4;
    uint32_t b_rel = (uint32_t)(warp_n0 + (lane & 7) + ((lane >> 4) << 3)) * 128;
    uint32_t b_sw  = lane & 7;
    uint32_t b_ch  = (lane >> 3) & 1;

    float acc[2][8][4];
    #pragma unroll
    for (int mt = 0; mt < 2; mt++)
        #pragma unroll
        for (int nt = 0; nt < 8; nt++)
            #pragma unroll
            for (int v = 0; v < 4; v++) acc[mt][nt][v] = 0.0f;

    // ---- prologue: fill 2 stages ----
    #pragma unroll
    for (int i = 0; i < STAGES - 1; i++) {
        uint32_t sA = sb + i * STAGE_BYTES;
        uint32_t sB = sA + A_BYTES;
        #pragma unroll
        for (int p = 0; p < 4; p++) { CP_ASYNC16(sA + offA[p], pA[p]); pA[p] += BK; }
        #pragma unroll
        for (int p = 0; p < 4; p++) { CP_ASYNC16(sB + offB[p], pB[p]); pB[p] += BK; }
        CP_COMMIT();
    }

    int s_comp = 0;              // stage computed this iter
    int s_load = STAGES - 1;     // stage filled this iter

    // ---- main loop ----
    #pragma unroll 1
    for (int i = 0; i < ITERS; i++) {
        CP_WAIT(STAGES - 2);     // own groups done => stage s_comp filled
        __syncthreads();         // all threads' waits passed => data visible;
                                 // also: all reads of stage s_load finished

        uint32_t As = sb + s_comp * STAGE_BYTES;
        uint32_t Bs = As + A_BYTES;
        uint32_t aBase = As + a_rel;
        uint32_t bBase = Bs + b_rel;

        // ---- ks0 fragment loads FIRST (tensor restart path) ----
        uint32_t a0[2][4];
        #pragma unroll
        for (int mt = 0; mt < 2; mt++) {
            uint32_t addr = aBase + mt * 2048 + ((a_co ^ a_sw) << 4);
            LDSM_X4(a0[mt][0], a0[mt][1], a0[mt][2], a0[mt][3], addr);
        }
        uint32_t b0[8][2];
        #pragma unroll
        for (int j = 0; j < 4; j++) {
            uint32_t addr = bBase + j * 2048 + ((b_ch ^ b_sw) << 4);
            uint32_t r0, r1, r2, r3;
            LDSM_X4(r0, r1, r2, r3, addr);
            b0[2 * j][0] = r0;      b0[2 * j][1] = r1;
            b0[2 * j + 1][0] = r2;  b0[2 * j + 1][1] = r3;
        }

        // ---- now issue next-stage cp.asyncs (hide under MMA burst) ----
        if (i + STAGES - 1 < ITERS) {
            uint32_t sA = sb + s_load * STAGE_BYTES;
            uint32_t sB = sA + A_BYTES;
            #pragma unroll
            for (int p = 0; p < 4; p++) { CP_ASYNC16(sA + offA[p], pA[p]); pA[p] += BK; }
            #pragma unroll
            for (int p = 0; p < 4; p++) { CP_ASYNC16(sB + offB[p], pB[p]); pB[p] += BK; }
        }
        CP_COMMIT();

        // ---- ks0 MMAs ----
        #pragma unroll
        for (int mt = 0; mt < 2; mt++)
            #pragma unroll
            for (int nt = 0; nt < 8; nt++)
                MMA_F16(acc[mt][nt], a0[mt], b0[nt]);

        // ---- ks1..3 ----
        #pragma unroll
        for (int ks = 1; ks < 4; ks++) {
            uint32_t a[2][4];
            #pragma unroll
            for (int mt = 0; mt < 2; mt++) {
                uint32_t addr = aBase + mt * 2048 +
                                ((((uint32_t)ks * 2 + a_co) ^ a_sw) << 4);
                LDSM_X4(a[mt][0], a[mt][1], a[mt][2], a[mt][3], addr);
            }
            uint32_t b[8][2];
            #pragma unroll
            for (int j = 0; j < 4; j++) {
                uint32_t addr = bBase + j * 2048 +
                                ((((uint32_t)ks * 2 + b_ch) ^ b_sw) << 4);
                uint32_t r0, r1, r2, r3;
                LDSM_X4(r0, r1, r2, r3, addr);
                b[2 * j][0] = r0;      b[2 * j][1] = r1;
                b[2 * j + 1][0] = r2;  b[2 * j + 1][1] = r3;
            }
            #pragma unroll
            for (int mt = 0; mt < 2; mt++)
                #pragma unroll
                for (int nt = 0; nt < 8; nt++)
                    MMA_F16(acc[mt][nt], a[mt], b[nt]);
        }

        if (++s_comp == STAGES) s_comp = 0;
        if (++s_load == STAGES) s_load = 0;
    }

    // ---- epilogue: direct global stores (float2) ----
    int row0 = tm * BM + warp_m0 + (lane >> 2);
    int col0 = tn * BN + warp_n0 + (lane & 3) * 2;
    #pragma unroll
    for (int mt = 0; mt < 2; mt++) {
        #pragma unroll
        for (int nt = 0; nt < 8; nt++) {
            int r = row0 + mt * 16;
            int c = col0 + nt * 8;
            float2* d0 = (float2*)(C + (size_t)r * N_DIM + c);
            float2* d1 = (float2*)(C + (size_t)(r + 8) * N_DIM + c);
            *d0 = make_float2(acc[mt][nt][0], acc[mt][nt][1]);
            *d1 = make_float2(acc[mt][nt][2], acc[mt][nt][3]);
        }
    }
}

// ============================================================================
// Host launcher
// ============================================================================
extern "C" void kernel_launch(void* const* d_in, const int* in_sizes, int n_in,
                              void* d_out, int out_size)
{
    const float* X = (const float*)d_in[0];   // [8192, 4096]
    const float* W = (const float*)d_in[1];   // [4096, 4096]
    float* C = (float*)d_out;                 // [8192, 4096]

    void* bt_ptr = nullptr;
    cudaGetSymbolAddress(&bt_ptr, g_Bth);
    void* xh_ptr = nullptr;
    cudaGetSymbolAddress(&xh_ptr, g_Xh);

    preprocess_kernel<<<(unsigned)(NXB + NTB), 256>>>(
        (const float4*)X, (uint4*)xh_ptr, W, (__half*)bt_ptr);

    cudaFuncSetAttribute(gemm_f16_kernel,
                         cudaFuncAttributeMaxDynamicSharedMemorySize, SMEM_TOTAL);
    gemm_f16_kernel<<<MT * NT, THREADS, SMEM_TOTAL>>>(
        (const __half*)xh_ptr, (const __half*)bt_ptr, C);
}

// round 17
// speedup vs baseline: 1.0782x; 1.0782x over previous
#include <cuda_runtime.h>
#include <cuda_fp16.h>
#include <cstdint>

// ============================================================================
// C[8192,4096] = X[8192,4096] @ W[4096,4096], fp32 in/out.
// FINAL (= R12, best measured: 678.0 us, rel_err 2.8e-4):
//   fp16 m16n8k16 mma.sync with fp32 accumulation. fp16 mantissa (10 bit)
//   == tf32 mantissa, so precision matches the tf32 path while doubling
//   MACs/instruction and halving smem traffic (BK=64 halves = 128B rows).
//   3-stage cp.async pipeline, proven ordering wait -> sync -> issue ->
//   compute; 256 thr = 8 warps (4m x 2n, warp tile 32x64), 128 regs,
//   2 CTAs/SM (= full register file, RF-optimal occupancy).
//   R13's LDSM-hoist reorder REVERTED (measured regression 678 -> 735 us:
//   LDSM and cp.async share the MIO issue path; hoisting only delays loads
//   and raises live-register pressure under the 128-reg cap).
// ============================================================================
#define M_DIM 8192
#define K_DIM 4096
#define N_DIM 4096

#define BM 128
#define BN 128
#define BK 64                         // 64 halves = 128 B rows
#define STAGES 3
#define ITERS (K_DIM / BK)            // 64
#define NT (N_DIM / BN)               // 32
#define MT (M_DIM / BM)               // 64
#define THREADS 256

#define A_BYTES (BM * BK * 2)         // 16384
#define B_BYTES (BN * BK * 2)         // 16384
#define STAGE_BYTES (A_BYTES + B_BYTES)   // 32768
#define SMEM_TOTAL (STAGES * STAGE_BYTES) // 98304

__device__ __half g_Bth[(size_t)N_DIM * K_DIM];  // 32 MB (fp16 W^T, [N,K])
__device__ __half g_Xh [(size_t)M_DIM * K_DIM];  // 64 MB (fp16 X)

// ============================================================================
// PTX helpers
// ============================================================================
__device__ __forceinline__ uint32_t smem_to_u32(const void* p) {
    uint32_t a;
    asm("{ .reg .u64 t; cvta.to.shared.u64 t, %1; cvt.u32.u64 %0, t; }"
        : "=r"(a) : "l"(p));
    return a;
}

#define CP_ASYNC16(smem_addr, gptr) \
    asm volatile("cp.async.cg.shared.global [%0], [%1], 16;" \
                 :: "r"(smem_addr), "l"(gptr) : "memory")
#define CP_COMMIT() asm volatile("cp.async.commit_group;" ::: "memory")
#define CP_WAIT(n)  asm volatile("cp.async.wait_group %0;" :: "n"(n) : "memory")

#define LDSM_X4(r0, r1, r2, r3, addr) \
    asm volatile("ldmatrix.sync.aligned.m8n8.x4.shared.b16 {%0,%1,%2,%3}, [%4];" \
                 : "=r"(r0), "=r"(r1), "=r"(r2), "=r"(r3) : "r"(addr))

#define MMA_F16(c, a, b) \
    asm volatile( \
        "mma.sync.aligned.m16n8k16.row.col.f32.f16.f16.f32 " \
        "{%0,%1,%2,%3}, {%4,%5,%6,%7}, {%8,%9}, {%0,%1,%2,%3};" \
        : "+f"((c)[0]), "+f"((c)[1]), "+f"((c)[2]), "+f"((c)[3]) \
        : "r"((a)[0]), "r"((a)[1]), "r"((a)[2]), "r"((a)[3]), \
          "r"((b)[0]), "r"((b)[1]))

// ============================================================================
// Kernel 0 (fused preprocessing):
//   blocks [0, NXB): convert X -> fp16 (8 floats -> 8 halves per thread)
//   blocks [NXB, NXB+NTB): transpose W[k][n] -> fp16 Bt[n][k] (32x32 tiles)
// ============================================================================
#define NXB ((M_DIM * (size_t)K_DIM / 8) / 256)      // 16384
#define NTB ((K_DIM / 32) * (N_DIM / 32))            // 16384

__global__ void __launch_bounds__(256) preprocess_kernel(
    const float4* __restrict__ X, uint4* __restrict__ Xh,
    const float* __restrict__ W, __half* __restrict__ Bt)
{
    __shared__ float t[32][33];
    unsigned bid = blockIdx.x;
    int tid = threadIdx.x;

    if (bid < NXB) {
        size_t i = (size_t)bid * 256 + tid;
        float4 v0 = X[2 * i];
        float4 v1 = X[2 * i + 1];
        __half2 h0 = __floats2half2_rn(v0.x, v0.y);
        __half2 h1 = __floats2half2_rn(v0.z, v0.w);
        __half2 h2 = __floats2half2_rn(v1.x, v1.y);
        __half2 h3 = __floats2half2_rn(v1.z, v1.w);
        uint4 out;
        out.x = *(uint32_t*)&h0;  out.y = *(uint32_t*)&h1;
        out.z = *(uint32_t*)&h2;  out.w = *(uint32_t*)&h3;
        Xh[i] = out;
    } else {
        unsigned b2 = bid - NXB;
        int bx = (b2 % (N_DIM / 32)) * 32;   // n block
        int by = (b2 / (N_DIM / 32)) * 32;   // k block
        int tx = tid & 31, ty = tid >> 5;    // 32 x 8
        #pragma unroll
        for (int j = 0; j < 32; j += 8)
            t[ty + j][tx] = W[(size_t)(by + ty + j) * N_DIM + (bx + tx)];
        __syncthreads();
        #pragma unroll
        for (int j = 0; j < 32; j += 8)
            Bt[(size_t)(bx + ty + j) * K_DIM + (by + tx)] =
                __float2half_rn(t[tx][ty + j]);
    }
}

// ============================================================================
// Kernel 1: fp16 mma.sync GEMM, 3-stage cp.async pipeline, 2 CTAs/SM
//   256 threads = 8 warps in 4(m) x 2(n); warp tile 32x64
//   Per-iter order (PROVEN): wait_group -> __syncthreads -> issue -> compute
// ============================================================================
__global__ void __launch_bounds__(THREADS, 2) gemm_f16_kernel(
    const __half* __restrict__ X,
    const __half* __restrict__ Bt,
    float* __restrict__ C)
{
    extern __shared__ __align__(1024) char smem[];
    uint32_t sb = smem_to_u32(smem);

    int tid  = threadIdx.x;
    int wid  = tid >> 5;
    int lane = tid & 31;
    int bid  = blockIdx.x;
    int tn   = bid % NT;
    int tm   = bid / NT;

    int wm = wid & 3;              // m group 0..3
    int wn = wid >> 2;             // n group 0..1
    int warp_m0 = wm * 32;
    int warp_n0 = wn * 64;

    // ---- cp.async precompute (4 chunks of 16B per operand per thread) ----
    uint32_t offA[4]; const __half* pA[4];
    uint32_t offB[4]; const __half* pB[4];
    #pragma unroll
    for (int p = 0; p < 4; p++) {
        int ca = tid + p * THREADS;
        int row = ca >> 3, c = ca & 7;
        uint32_t off = row * 128 + ((c ^ (row & 7)) << 4);
        offA[p] = off;
        offB[p] = off;
        pA[p] = X  + (size_t)(tm * BM + row) * K_DIM + c * 8;
        pB[p] = Bt + (size_t)(tn * BN + row) * K_DIM + c * 8;
    }

    // ---- ldmatrix per-lane address components ----
    uint32_t a_rel = (uint32_t)(warp_m0 + (lane & 15)) * 128;
    uint32_t a_sw  = lane & 7;
    uint32_t a_co  = lane >> 4;
    uint32_t b_rel = (uint32_t)(warp_n0 + (lane & 7) + ((lane >> 4) << 3)) * 128;
    uint32_t b_sw  = lane & 7;
    uint32_t b_ch  = (lane >> 3) & 1;

    float acc[2][8][4];
    #pragma unroll
    for (int mt = 0; mt < 2; mt++)
        #pragma unroll
        for (int nt = 0; nt < 8; nt++)
            #pragma unroll
            for (int v = 0; v < 4; v++) acc[mt][nt][v] = 0.0f;

    // ---- prologue: fill 2 stages ----
    #pragma unroll
    for (int i = 0; i < STAGES - 1; i++) {
        uint32_t sA = sb + i * STAGE_BYTES;
        uint32_t sB = sA + A_BYTES;
        #pragma unroll
        for (int p = 0; p < 4; p++) { CP_ASYNC16(sA + offA[p], pA[p]); pA[p] += BK; }
        #pragma unroll
        for (int p = 0; p < 4; p++) { CP_ASYNC16(sB + offB[p], pB[p]); pB[p] += BK; }
        CP_COMMIT();
    }

    int s_comp = 0;              // stage computed this iter
    int s_load = STAGES - 1;     // stage filled this iter

    // ---- main loop ----
    #pragma unroll 1
    for (int i = 0; i < ITERS; i++) {
        CP_WAIT(STAGES - 2);     // own groups done => stage s_comp filled
        __syncthreads();         // all threads' waits passed => data visible;
                                 // also: all reads of stage s_load finished

        if (i + STAGES - 1 < ITERS) {
            uint32_t sA = sb + s_load * STAGE_BYTES;
            uint32_t sB = sA + A_BYTES;
            #pragma unroll
            for (int p = 0; p < 4; p++) { CP_ASYNC16(sA + offA[p], pA[p]); pA[p] += BK; }
            #pragma unroll
            for (int p = 0; p < 4; p++) { CP_ASYNC16(sB + offB[p], pB[p]); pB[p] += BK; }
        }
        CP_COMMIT();

        uint32_t As = sb + s_comp * STAGE_BYTES;
        uint32_t Bs = As + A_BYTES;
        uint32_t aBase = As + a_rel;
        uint32_t bBase = Bs + b_rel;

        #pragma unroll
        for (int ks = 0; ks < 4; ks++) {       // 4 x k16 = BK 64 halves
            uint32_t a[2][4];
            #pragma unroll
            for (int mt = 0; mt < 2; mt++) {
                uint32_t addr = aBase + mt * 2048 +
                                ((((uint32_t)ks * 2 + a_co) ^ a_sw) << 4);
                LDSM_X4(a[mt][0], a[mt][1], a[mt][2], a[mt][3], addr);
            }
            uint32_t b[8][2];
            #pragma unroll
            for (int j = 0; j < 4; j++) {
                uint32_t addr = bBase + j * 2048 +
                                ((((uint32_t)ks * 2 + b_ch) ^ b_sw) << 4);
                uint32_t r0, r1, r2, r3;
                LDSM_X4(r0, r1, r2, r3, addr);
                b[2 * j][0] = r0;      b[2 * j][1] = r1;
                b[2 * j + 1][0] = r2;  b[2 * j + 1][1] = r3;
            }
            #pragma unroll
            for (int mt = 0; mt < 2; mt++)
                #pragma unroll
                for (int nt = 0; nt < 8; nt++)
                    MMA_F16(acc[mt][nt], a[mt], b[nt]);
        }

        if (++s_comp == STAGES) s_comp = 0;
        if (++s_load == STAGES) s_load = 0;
    }

    // ---- epilogue: direct global stores (float2) ----
    int row0 = tm * BM + warp_m0 + (lane >> 2);
    int col0 = tn * BN + warp_n0 + (lane & 3) * 2;
    #pragma unroll
    for (int mt = 0; mt < 2; mt++) {
        #pragma unroll
        for (int nt = 0; nt < 8; nt++) {
            int r = row0 + mt * 16;
            int c = col0 + nt * 8;
            float2* d0 = (float2*)(C + (size_t)r * N_DIM + c);
            float2* d1 = (float2*)(C + (size_t)(r + 8) * N_DIM + c);
            *d0 = make_float2(acc[mt][nt][0], acc[mt][nt][1]);
            *d1 = make_float2(acc[mt][nt][2], acc[mt][nt][3]);
        }
    }
}

// ============================================================================
// Host launcher
// ============================================================================
extern "C" void kernel_launch(void* const* d_in, const int* in_sizes, int n_in,
                              void* d_out, int out_size)
{
    const float* X = (const float*)d_in[0];   // [8192, 4096]
    const float* W = (const float*)d_in[1];   // [4096, 4096]
    float* C = (float*)d_out;                 // [8192, 4096]

    void* bt_ptr = nullptr;
    cudaGetSymbolAddress(&bt_ptr, g_Bth);
    void* xh_ptr = nullptr;
    cudaGetSymbolAddress(&xh_ptr, g_Xh);

    preprocess_kernel<<<(unsigned)(NXB + NTB), 256>>>(
        (const float4*)X, (uint4*)xh_ptr, W, (__half*)bt_ptr);

    cudaFuncSetAttribute(gemm_f16_kernel,
                         cudaFuncAttributeMaxDynamicSharedMemorySize, SMEM_TOTAL);
    gemm_f16_kernel<<<MT * NT, THREADS, SMEM_TOTAL>>>(
        (const __half*)xh_ptr, (const __half*)bt_ptr, C);
}